// round 7
// baseline (speedup 1.0000x reference)
#include <cuda_runtime.h>
#include <cfloat>

#define NB    2
#define CC    256
#define HH    64
#define WW    64
#define KK    128
#define PH    7
#define PW    7

__global__ __launch_bounds__(256) void roipool_kernel(
    const float* __restrict__ x,     // [N, C, H, W]
    const float* __restrict__ rois,  // [K, 5]
    float* __restrict__ out,         // [K, C, 7, 7]
    int total)
{
    int idx = blockIdx.x * blockDim.x + threadIdx.x;
    if (idx >= total) return;

    int pw = idx % PW;
    int ph = (idx / PW) % PH;
    int c  = (idx / (PW * PH)) % CC;
    int k  = idx / (PW * PH * CC);

    const float* r = rois + k * 5;
    int b  = (int)__ldg(r + 0);
    // IEEE RN multiply (0.0625 is exact), round half-to-even like jnp.round
    int x1 = (int)rintf(__fmul_rn(__ldg(r + 1), 0.0625f));
    int y1 = (int)rintf(__fmul_rn(__ldg(r + 2), 0.0625f));
    int x2 = (int)rintf(__fmul_rn(__ldg(r + 3), 0.0625f));
    int y2 = (int)rintf(__fmul_rn(__ldg(r + 4), 0.0625f));

    int roi_w = max(x2 - x1 + 1, 1);
    int roi_h = max(y2 - y1 + 1, 1);

    // XLA rewrites (x / 7) -> x * RN(1/7). Replicate exactly:
    // RN(1/7) as f32 = 0x3E124925 = 0.14285714924335479736328125
    const float RECIP7 = __int_as_float(0x3E124925);
    float bw = __fmul_rn((float)roi_w, RECIP7);
    float bh = __fmul_rn((float)roi_h, RECIP7);

    int ws = (int)floorf(__fmul_rn((float)pw,       bw)) + x1;
    int we = (int)ceilf (__fmul_rn((float)(pw + 1), bw)) + x1;
    int hs = (int)floorf(__fmul_rn((float)ph,       bh)) + y1;
    int he = (int)ceilf (__fmul_rn((float)(ph + 1), bh)) + y1;

    ws = min(max(ws, 0), WW);
    we = min(max(we, 0), WW);
    hs = min(max(hs, 0), HH);
    he = min(max(he, 0), HH);

    float m = 0.0f;
    if (hs < he && ws < we) {
        m = -FLT_MAX;
        const float* plane = x + ((size_t)b * CC + c) * (HH * WW);
        for (int h = hs; h < he; ++h) {
            const float* row = plane + h * WW;
            #pragma unroll 4
            for (int w = ws; w < we; ++w) {
                m = fmaxf(m, __ldg(row + w));
            }
        }
    }
    out[idx] = m;
}

extern "C" void kernel_launch(void* const* d_in, const int* in_sizes, int n_in,
                              void* d_out, int out_size)
{
    // Defensive: identify inputs by size (input = 2*256*64*64, rois = 128*5)
    const float* x    = (const float*)d_in[0];
    const float* rois = (const float*)d_in[1];
    if (n_in >= 2 && in_sizes[0] < in_sizes[1]) {
        x    = (const float*)d_in[1];
        rois = (const float*)d_in[0];
    }
    float* out = (float*)d_out;

    int total = KK * CC * PH * PW;  // 1,605,632
    int threads = 256;
    int blocks = (total + threads - 1) / threads;
    roipool_kernel<<<blocks, threads>>>(x, rois, out, total);
}